// round 6
// baseline (speedup 1.0000x reference)
#include <cuda_runtime.h>
#include <cstdint>

#define NN 50000
#define EE 600000
#define DD 128
#define HH 8
#define SCALE 0.25f   // (128/8)^-0.5

// ---------------- scratch (static device allocations; no cudaMalloc) ----------
__device__ __align__(16) float g_q[(size_t)NN * DD];
__device__ __align__(16) float g_k[(size_t)NN * DD];
__device__ __align__(16) float g_v[(size_t)NN * DD];
__device__ __align__(16) float g_acc[(size_t)NN * DD];
__device__ __align__(16) float g_G[(size_t)NN * 512];   // per-node, per-head We-projected q
__device__ float g_c[(size_t)NN * HH];                  // q . be per head
__device__ int   g_cnt[NN];
__device__ int   g_off[NN + 1];
__device__ int   g_cur[NN];
__device__ int2  g_sedge[EE];                           // (src, eid) sorted by dst

// ---------------- tf32 helpers -------------------------------------------------
__device__ __forceinline__ uint32_t tf32cvt(float v) {
    uint32_t r; asm("cvt.rna.tf32.f32 %0, %1;" : "=r"(r) : "f"(v)); return r;
}
__device__ __forceinline__ void mma_tf32(float c[4], const uint32_t a[4],
                                         uint32_t b0, uint32_t b1) {
    asm volatile(
        "mma.sync.aligned.m16n8k8.row.col.f32.tf32.tf32.f32 "
        "{%0,%1,%2,%3}, {%4,%5,%6,%7}, {%8,%9}, {%0,%1,%2,%3};"
        : "+f"(c[0]), "+f"(c[1]), "+f"(c[2]), "+f"(c[3])
        : "r"(a[0]), "r"(a[1]), "r"(a[2]), "r"(a[3]), "r"(b0), "r"(b1));
}

#define SA_PAD 132
#define SW_PAD 136
#define GEMM_SMEM ((64 * SA_PAD + 2 * 128 * SW_PAD) * 4)

// ---------------- tensor-core GEMM: C[M,128] = A[M,128] @ W[128,128] + b ------
// tf32x3: A = Ah + Al (registers), W = Wh + Wl (smem); C += AhBh + AlBh + AhBl.
// 256 threads = 8 warps (4 m-rows x 2 n-cols); warp tile 16x64.
__global__ void __launch_bounds__(256) k_gemm_tc(
    const float* __restrict__ A, const float* __restrict__ W,
    const float* __restrict__ bias, float* __restrict__ C, int M)
{
    extern __shared__ float sm[];
    float*    sA  = sm;                                   // [64][SA_PAD]
    uint32_t* sWh = (uint32_t*)(sm + 64 * SA_PAD);        // [128][SW_PAD]
    uint32_t* sWl = sWh + 128 * SW_PAD;

    int tid = threadIdx.x;
    int row0 = blockIdx.x * 64;

    // load A tile (fp32, unsplit)
    for (int i = tid; i < 64 * 32; i += 256) {
        int r = i >> 5, c4 = i & 31;
        float4 a = make_float4(0.f, 0.f, 0.f, 0.f);
        if (row0 + r < M)
            a = *(const float4*)(A + (size_t)(row0 + r) * 128 + c4 * 4);
        float* d = sA + r * SA_PAD + c4 * 4;
        d[0] = a.x; d[1] = a.y; d[2] = a.z; d[3] = a.w;
    }
    // load + split W
    for (int i = tid; i < 128 * 32; i += 256) {
        int r = i >> 5, c4 = i & 31;
        float4 w = *(const float4*)(W + (size_t)r * 128 + c4 * 4);
        uint32_t* dh = sWh + r * SW_PAD + c4 * 4;
        uint32_t* dl = sWl + r * SW_PAD + c4 * 4;
        float wv[4] = {w.x, w.y, w.z, w.w};
#pragma unroll
        for (int j = 0; j < 4; j++) {
            uint32_t hi = tf32cvt(wv[j]);
            dh[j] = hi;
            dl[j] = tf32cvt(wv[j] - __uint_as_float(hi));
        }
    }
    __syncthreads();

    int lane = tid & 31, wid = tid >> 5;
    int g = lane >> 2, t4 = lane & 3;
    int wm = wid >> 1, wn = wid & 1;
    int mrow = wm * 16;

    float c[8][4];
#pragma unroll
    for (int nt = 0; nt < 8; nt++)
#pragma unroll
        for (int j = 0; j < 4; j++) c[nt][j] = 0.f;

#pragma unroll
    for (int kt = 0; kt < 16; kt++) {
        int k0 = kt * 8;
        float af[4];
        af[0] = sA[(mrow + g) * SA_PAD + k0 + t4];
        af[1] = sA[(mrow + g + 8) * SA_PAD + k0 + t4];
        af[2] = sA[(mrow + g) * SA_PAD + k0 + t4 + 4];
        af[3] = sA[(mrow + g + 8) * SA_PAD + k0 + t4 + 4];
        uint32_t ah[4], al[4];
#pragma unroll
        for (int j = 0; j < 4; j++) {
            ah[j] = tf32cvt(af[j]);
            al[j] = tf32cvt(af[j] - __uint_as_float(ah[j]));
        }
#pragma unroll
        for (int nt = 0; nt < 8; nt++) {
            int n = wn * 64 + nt * 8 + g;
            uint32_t bh0 = sWh[(k0 + t4) * SW_PAD + n];
            uint32_t bh1 = sWh[(k0 + t4 + 4) * SW_PAD + n];
            uint32_t bl0 = sWl[(k0 + t4) * SW_PAD + n];
            uint32_t bl1 = sWl[(k0 + t4 + 4) * SW_PAD + n];
            mma_tf32(c[nt], ah, bh0, bh1);
            mma_tf32(c[nt], al, bh0, bh1);
            mma_tf32(c[nt], ah, bl0, bl1);
        }
    }

#pragma unroll
    for (int nt = 0; nt < 8; nt++) {
        int n = wn * 64 + nt * 8 + 2 * t4;
        float2 b2 = *(const float2*)(bias + n);
        int m0 = row0 + mrow + g;
        if (m0 < M) {
            float2 o = make_float2(c[nt][0] + b2.x, c[nt][1] + b2.y);
            *(float2*)(C + (size_t)m0 * 128 + n) = o;
        }
        int m1 = m0 + 8;
        if (m1 < M) {
            float2 o = make_float2(c[nt][2] + b2.x, c[nt][3] + b2.y);
            *(float2*)(C + (size_t)m1 * 128 + n) = o;
        }
    }
}

// ---------------- G transform -------------------------------------------------
// G[n,h,j] = sum_{i<16} q[n, 16h+i] * We[j, 16h+i]   (j in [0,64))
// c[n,h]   = sum_{i<16} q[n, 16h+i] * be[16h+i]
__global__ void __launch_bounds__(256) k_G(
    const float* __restrict__ We, const float* __restrict__ be, int N)
{
    int b = blockIdx.x;
    int h = b & 7;
    int n0 = (b >> 3) * 64;
    __shared__ float sQ[16][68];
    __shared__ float sW[16][68];
    __shared__ float sbe[16];
    int t = threadIdx.x;

    {
        int node = t & 63, ib = t >> 6;
        float4 v = make_float4(0.f, 0.f, 0.f, 0.f);
        if (n0 + node < N)
            v = *(const float4*)(g_q + (size_t)(n0 + node) * 128 + h * 16 + ib * 4);
        sQ[ib * 4 + 0][node] = v.x;
        sQ[ib * 4 + 1][node] = v.y;
        sQ[ib * 4 + 2][node] = v.z;
        sQ[ib * 4 + 3][node] = v.w;

        int j = node;
        float4 w = *(const float4*)(We + (size_t)j * 128 + h * 16 + ib * 4);
        sW[ib * 4 + 0][j] = w.x;
        sW[ib * 4 + 1][j] = w.y;
        sW[ib * 4 + 2][j] = w.z;
        sW[ib * 4 + 3][j] = w.w;
    }
    if (t < 16) sbe[t] = be[h * 16 + t];
    __syncthreads();

    int tn = t >> 4, tj = t & 15;
    float acc[4][4];
#pragma unroll
    for (int r = 0; r < 4; r++)
#pragma unroll
        for (int s = 0; s < 4; s++) acc[r][s] = 0.f;

#pragma unroll
    for (int i = 0; i < 16; i++) {
        float qv[4], wv[4];
#pragma unroll
        for (int r = 0; r < 4; r++) qv[r] = sQ[i][tn * 4 + r];
#pragma unroll
        for (int s = 0; s < 4; s++) wv[s] = sW[i][tj * 4 + s];
#pragma unroll
        for (int r = 0; r < 4; r++)
#pragma unroll
            for (int s = 0; s < 4; s++) acc[r][s] += qv[r] * wv[s];
    }

#pragma unroll
    for (int r = 0; r < 4; r++) {
        int n = n0 + tn * 4 + r;
        if (n < N) {
            float4 o = make_float4(acc[r][0], acc[r][1], acc[r][2], acc[r][3]);
            *(float4*)(g_G + (size_t)n * 512 + h * 64 + tj * 4) = o;
        }
    }

    if (t < 64) {
        int n = n0 + t;
        if (n < N) {
            float s = 0.f;
#pragma unroll
            for (int i = 0; i < 16; i++) s += sQ[i][t] * sbe[i];
            g_c[(size_t)n * 8 + h] = s;
        }
    }
}

// ---------------- counting sort by dst ----------------------------------------
__global__ void k_zero_cnt(int N) {
    int i = blockIdx.x * blockDim.x + threadIdx.x;
    if (i < N) g_cnt[i] = 0;
}

__global__ void k_hist(const int* __restrict__ ei, int E) {
    int i = blockIdx.x * blockDim.x + threadIdx.x;
    if (i < E) atomicAdd(&g_cnt[ei[E + i]], 1);
}

__global__ void __launch_bounds__(1024) k_scan(int N) {
    __shared__ int s_sums[1024];
    int t = threadIdx.x;
    int chunk = (N + 1023) / 1024;
    int beg = t * chunk;
    int end = min(beg + chunk, N);
    int s = 0;
    for (int i = beg; i < end; i++) s += g_cnt[i];
    s_sums[t] = s;
    __syncthreads();
    for (int d = 1; d < 1024; d <<= 1) {
        int v = (t >= d) ? s_sums[t - d] : 0;
        __syncthreads();
        s_sums[t] += v;
        __syncthreads();
    }
    int run = (t == 0) ? 0 : s_sums[t - 1];
    for (int i = beg; i < end; i++) {
        int c = g_cnt[i];
        g_off[i] = run;
        g_cur[i] = run;
        run += c;
    }
    if (t == 1023) g_off[N] = s_sums[1023];
}

__global__ void k_scatter(const int* __restrict__ ei, int E) {
    int i = blockIdx.x * blockDim.x + threadIdx.x;
    if (i >= E) return;
    int dst = ei[E + i];
    int pos = atomicAdd(&g_cur[dst], 1);
    g_sedge[pos] = make_int2(ei[i], i);
}

// ---------------- fused attention: one warp per destination node --------------
// Single pass, no smem, no intra-loop syncs; 2-edge unroll for MLP.
__global__ void __launch_bounds__(256) k_attn(
    const float* __restrict__ ea, int N)
{
    int lane = threadIdx.x & 31;
    int dst = (blockIdx.x * 256 + threadIdx.x) >> 5;
    if (dst >= N) return;

    int h = lane >> 2, p = lane & 3;
    int beg = g_off[dst], end = g_off[dst + 1];

    const float4* q4 = (const float4*)g_q;
    const float4* k4 = (const float4*)g_k;
    const float4* v4 = (const float4*)g_v;

    float4 qv = q4[(size_t)dst * 32 + lane];
    float4 Gr[4];
    {
        const float4* Gp = (const float4*)(g_G + (size_t)dst * 512 + h * 64 + p * 16);
#pragma unroll
        for (int i = 0; i < 4; i++) Gr[i] = Gp[i];
    }
    float cc = g_c[(size_t)dst * 8 + h];

    float denom = 0.f;
    float4 acc = make_float4(0.f, 0.f, 0.f, 0.f);

    int e = beg;
    for (; e + 2 <= end; e += 2) {
        int2 s0 = g_sedge[e];
        int2 s1 = g_sedge[e + 1];
        float4 kv0 = k4[(size_t)s0.x * 32 + lane];
        float4 kv1 = k4[(size_t)s1.x * 32 + lane];
        float4 vv0 = v4[(size_t)s0.x * 32 + lane];
        float4 vv1 = v4[(size_t)s1.x * 32 + lane];
        const float4* a0p = (const float4*)(ea + (size_t)s0.y * 64) + p * 4;
        const float4* a1p = (const float4*)(ea + (size_t)s1.y * 64) + p * 4;

        float t0 = qv.x * kv0.x + qv.y * kv0.y + qv.z * kv0.z + qv.w * kv0.w;
        float t1 = qv.x * kv1.x + qv.y * kv1.y + qv.z * kv1.z + qv.w * kv1.w;
#pragma unroll
        for (int i = 0; i < 4; i++) {
            float4 a0 = a0p[i];
            t0 += a0.x * Gr[i].x + a0.y * Gr[i].y + a0.z * Gr[i].z + a0.w * Gr[i].w;
        }
#pragma unroll
        for (int i = 0; i < 4; i++) {
            float4 a1 = a1p[i];
            t1 += a1.x * Gr[i].x + a1.y * Gr[i].y + a1.z * Gr[i].z + a1.w * Gr[i].w;
        }
        t0 += __shfl_down_sync(0xffffffffu, t0, 1);
        t0 += __shfl_down_sync(0xffffffffu, t0, 2);
        t1 += __shfl_down_sync(0xffffffffu, t1, 1);
        t1 += __shfl_down_sync(0xffffffffu, t1, 2);

        float ex0 = 0.f, ex1 = 0.f;
        if (p == 0) {
            ex0 = __expf((t0 + cc) * SCALE);
            ex1 = __expf((t1 + cc) * SCALE);
            denom += ex0 + ex1;
        }
        ex0 = __shfl_sync(0xffffffffu, ex0, lane & ~3);
        ex1 = __shfl_sync(0xffffffffu, ex1, lane & ~3);
        acc.x += ex0 * vv0.x + ex1 * vv1.x;
        acc.y += ex0 * vv0.y + ex1 * vv1.y;
        acc.z += ex0 * vv0.z + ex1 * vv1.z;
        acc.w += ex0 * vv0.w + ex1 * vv1.w;
    }
    if (e < end) {
        int2 s0 = g_sedge[e];
        float4 kv0 = k4[(size_t)s0.x * 32 + lane];
        float4 vv0 = v4[(size_t)s0.x * 32 + lane];
        const float4* a0p = (const float4*)(ea + (size_t)s0.y * 64) + p * 4;
        float t0 = qv.x * kv0.x + qv.y * kv0.y + qv.z * kv0.z + qv.w * kv0.w;
#pragma unroll
        for (int i = 0; i < 4; i++) {
            float4 a0 = a0p[i];
            t0 += a0.x * Gr[i].x + a0.y * Gr[i].y + a0.z * Gr[i].z + a0.w * Gr[i].w;
        }
        t0 += __shfl_down_sync(0xffffffffu, t0, 1);
        t0 += __shfl_down_sync(0xffffffffu, t0, 2);
        float ex0 = 0.f;
        if (p == 0) {
            ex0 = __expf((t0 + cc) * SCALE);
            denom += ex0;
        }
        ex0 = __shfl_sync(0xffffffffu, ex0, lane & ~3);
        acc.x += ex0 * vv0.x;
        acc.y += ex0 * vv0.y;
        acc.z += ex0 * vv0.z;
        acc.w += ex0 * vv0.w;
    }

    float inv = (p == 0 && denom != 0.f) ? (1.f / denom) : 0.f;
    inv = __shfl_sync(0xffffffffu, inv, lane & ~3);
    acc.x *= inv; acc.y *= inv; acc.z *= inv; acc.w *= inv;
    *(float4*)(g_acc + (size_t)dst * 128 + lane * 4) = acc;
}

// ---------------- launch ------------------------------------------------------
extern "C" void kernel_launch(void* const* d_in, const int* in_sizes, int n_in,
                              void* d_out, int out_size)
{
    const float* x  = (const float*)d_in[0];
    const float* ea = (const float*)d_in[1];
    const float* Wq = (const float*)d_in[2];
    const float* bq = (const float*)d_in[3];
    const float* Wk = (const float*)d_in[4];
    const float* bk = (const float*)d_in[5];
    const float* Wv = (const float*)d_in[6];
    const float* bv = (const float*)d_in[7];
    const float* We = (const float*)d_in[8];
    const float* be = (const float*)d_in[9];
    const float* Wo = (const float*)d_in[10];
    const float* bo = (const float*)d_in[11];
    const int*   ei = (const int*)d_in[12];

    int N = in_sizes[0] / DD;
    int E = in_sizes[12] / 2;

    float* qp;   cudaGetSymbolAddress((void**)&qp,   g_q);
    float* kp;   cudaGetSymbolAddress((void**)&kp,   g_k);
    float* vp;   cudaGetSymbolAddress((void**)&vp,   g_v);
    float* accp; cudaGetSymbolAddress((void**)&accp, g_acc);

    cudaFuncSetAttribute(k_gemm_tc, cudaFuncAttributeMaxDynamicSharedMemorySize,
                         GEMM_SMEM);

    // sort edges by dst
    k_zero_cnt<<<(N + 255) / 256, 256>>>(N);
    k_hist<<<(E + 255) / 256, 256>>>(ei, E);
    k_scan<<<1, 1024>>>(N);
    k_scatter<<<(E + 255) / 256, 256>>>(ei, E);

    int gb = (N + 63) / 64;
    k_gemm_tc<<<gb, 256, GEMM_SMEM>>>(x, Wq, bq, qp, N);
    k_gemm_tc<<<gb, 256, GEMM_SMEM>>>(x, Wk, bk, kp, N);
    k_gemm_tc<<<gb, 256, GEMM_SMEM>>>(x, Wv, bv, vp, N);

    k_G<<<gb * 8, 256>>>(We, be, N);

    k_attn<<<(N + 7) / 8, 256>>>(ea, N);

    k_gemm_tc<<<gb, 256, GEMM_SMEM>>>(accp, Wo, bo, (float*)d_out, N);
}

// round 7
// speedup vs baseline: 1.2115x; 1.2115x over previous
#include <cuda_runtime.h>
#include <cstdint>

#define NN 50000
#define EE 600000
#define DD 128
#define HH 8
#define SCALE 0.25f   // (128/8)^-0.5

// ---------------- scratch (static device allocations; no cudaMalloc) ----------
__device__ __align__(16) float g_q[(size_t)NN * DD];
__device__ __align__(16) float g_k[(size_t)NN * DD];
__device__ __align__(16) float g_v[(size_t)NN * DD];
__device__ __align__(16) float g_acc[(size_t)NN * DD];
__device__ __align__(16) float g_G[(size_t)NN * 512];   // per-node, per-head We-projected q
__device__ float g_c[(size_t)NN * HH];                  // q . be per head
__device__ int   g_cnt[NN];
__device__ int   g_off[NN + 1];
__device__ int   g_cur[NN];
__device__ int2  g_sedge[EE];                           // (src, eid) sorted by dst

// ---------------- GEMM: C[M,128] = A[M,128] @ W[128,128] + b ------------------
// BM=64, BN=128 (full), BK=16; 256 threads; 8x4 micro-tile per thread. (proven)
__global__ void __launch_bounds__(256) k_gemm128(
    const float* __restrict__ A, const float* __restrict__ W,
    const float* __restrict__ bias, float* __restrict__ C, int M)
{
    __shared__ float sA[16][64];
    __shared__ float sW[16][128];
    int tid = threadIdx.x;
    int tx = tid & 31;
    int ty = tid >> 5;
    int row0 = blockIdx.x * 64;

    float acc[8][4];
#pragma unroll
    for (int i = 0; i < 8; i++)
#pragma unroll
        for (int j = 0; j < 4; j++) acc[i][j] = 0.f;

    for (int k0 = 0; k0 < 128; k0 += 16) {
        {
            int m = tid >> 2, q = tid & 3;
            float4 a = make_float4(0.f, 0.f, 0.f, 0.f);
            if (row0 + m < M)
                a = *(const float4*)(A + (size_t)(row0 + m) * 128 + k0 + q * 4);
            sA[q * 4 + 0][m] = a.x;
            sA[q * 4 + 1][m] = a.y;
            sA[q * 4 + 2][m] = a.z;
            sA[q * 4 + 3][m] = a.w;
        }
#pragma unroll
        for (int i = 0; i < 2; i++) {
            int idx = tid + i * 256;
            int r = idx >> 5, c4 = idx & 31;
            *(float4*)&sW[r][c4 * 4] =
                *(const float4*)(W + (size_t)(k0 + r) * 128 + c4 * 4);
        }
        __syncthreads();
#pragma unroll
        for (int k = 0; k < 16; k++) {
            float4 w = *(float4*)&sW[k][tx * 4];
#pragma unroll
            for (int i = 0; i < 8; i++) {
                float av = sA[k][ty * 8 + i];
                acc[i][0] += av * w.x;
                acc[i][1] += av * w.y;
                acc[i][2] += av * w.z;
                acc[i][3] += av * w.w;
            }
        }
        __syncthreads();
    }

    float4 b4 = *(const float4*)(bias + tx * 4);
#pragma unroll
    for (int i = 0; i < 8; i++) {
        int m = row0 + ty * 8 + i;
        if (m < M) {
            float4 o = make_float4(acc[i][0] + b4.x, acc[i][1] + b4.y,
                                   acc[i][2] + b4.z, acc[i][3] + b4.w);
            *(float4*)(C + (size_t)m * 128 + tx * 4) = o;
        }
    }
}

// ---------------- G transform -------------------------------------------------
// G[n,h,j] = sum_{i<16} q[n, 16h+i] * We[j, 16h+i]   (j in [0,64))
// c[n,h]   = sum_{i<16} q[n, 16h+i] * be[16h+i]
__global__ void __launch_bounds__(256) k_G(
    const float* __restrict__ We, const float* __restrict__ be, int N)
{
    int b = blockIdx.x;
    int h = b & 7;
    int n0 = (b >> 3) * 64;
    __shared__ float sQ[16][68];
    __shared__ float sW[16][68];
    __shared__ float sbe[16];
    int t = threadIdx.x;

    {
        int node = t & 63, ib = t >> 6;
        float4 v = make_float4(0.f, 0.f, 0.f, 0.f);
        if (n0 + node < N)
            v = *(const float4*)(g_q + (size_t)(n0 + node) * 128 + h * 16 + ib * 4);
        sQ[ib * 4 + 0][node] = v.x;
        sQ[ib * 4 + 1][node] = v.y;
        sQ[ib * 4 + 2][node] = v.z;
        sQ[ib * 4 + 3][node] = v.w;

        int j = node;
        float4 w = *(const float4*)(We + (size_t)j * 128 + h * 16 + ib * 4);
        sW[ib * 4 + 0][j] = w.x;
        sW[ib * 4 + 1][j] = w.y;
        sW[ib * 4 + 2][j] = w.z;
        sW[ib * 4 + 3][j] = w.w;
    }
    if (t < 16) sbe[t] = be[h * 16 + t];
    __syncthreads();

    int tn = t >> 4, tj = t & 15;
    float acc[4][4];
#pragma unroll
    for (int r = 0; r < 4; r++)
#pragma unroll
        for (int s = 0; s < 4; s++) acc[r][s] = 0.f;

#pragma unroll
    for (int i = 0; i < 16; i++) {
        float qv[4], wv[4];
#pragma unroll
        for (int r = 0; r < 4; r++) qv[r] = sQ[i][tn * 4 + r];
#pragma unroll
        for (int s = 0; s < 4; s++) wv[s] = sW[i][tj * 4 + s];
#pragma unroll
        for (int r = 0; r < 4; r++)
#pragma unroll
            for (int s = 0; s < 4; s++) acc[r][s] += qv[r] * wv[s];
    }

#pragma unroll
    for (int r = 0; r < 4; r++) {
        int n = n0 + tn * 4 + r;
        if (n < N) {
            float4 o = make_float4(acc[r][0], acc[r][1], acc[r][2], acc[r][3]);
            *(float4*)(g_G + (size_t)n * 512 + h * 64 + tj * 4) = o;
        }
    }

    if (t < 64) {
        int n = n0 + t;
        if (n < N) {
            float s = 0.f;
#pragma unroll
            for (int i = 0; i < 16; i++) s += sQ[i][t] * sbe[i];
            g_c[(size_t)n * 8 + h] = s;
        }
    }
}

// ---------------- counting sort by dst ----------------------------------------
__global__ void k_zero_cnt(int N) {
    int i = blockIdx.x * blockDim.x + threadIdx.x;
    if (i < N) g_cnt[i] = 0;
}

__global__ void k_hist(const int* __restrict__ ei, int E) {
    int i = blockIdx.x * blockDim.x + threadIdx.x;
    if (i < E) atomicAdd(&g_cnt[ei[E + i]], 1);
}

__global__ void __launch_bounds__(1024) k_scan(int N) {
    __shared__ int s_sums[1024];
    int t = threadIdx.x;
    int chunk = (N + 1023) / 1024;
    int beg = t * chunk;
    int end = min(beg + chunk, N);
    int s = 0;
    for (int i = beg; i < end; i++) s += g_cnt[i];
    s_sums[t] = s;
    __syncthreads();
    for (int d = 1; d < 1024; d <<= 1) {
        int v = (t >= d) ? s_sums[t - d] : 0;
        __syncthreads();
        s_sums[t] += v;
        __syncthreads();
    }
    int run = (t == 0) ? 0 : s_sums[t - 1];
    for (int i = beg; i < end; i++) {
        int c = g_cnt[i];
        g_off[i] = run;
        g_cur[i] = run;
        run += c;
    }
    if (t == 1023) g_off[N] = s_sums[1023];
}

__global__ void k_scatter(const int* __restrict__ ei, int E) {
    int i = blockIdx.x * blockDim.x + threadIdx.x;
    if (i >= E) return;
    int dst = ei[E + i];
    int pos = atomicAdd(&g_cur[dst], 1);
    g_sedge[pos] = make_int2(ei[i], i);
}

// ---------------- fused attention: one warp per destination node --------------
// Single pass, no smem, no intra-loop syncs; 2-edge unroll; xor-shfl reduction
// puts the group sum in all 4 lanes -> all-lane exp, per-lane denom (no bcast).
__global__ void __launch_bounds__(128) k_attn(
    const float* __restrict__ ea, int N)
{
    int lane = threadIdx.x & 31;
    int dst = (blockIdx.x * 128 + threadIdx.x) >> 5;
    if (dst >= N) return;

    int h = lane >> 2, p = lane & 3;
    int beg = g_off[dst], end = g_off[dst + 1];

    const float4* q4 = (const float4*)g_q;
    const float4* k4 = (const float4*)g_k;
    const float4* v4 = (const float4*)g_v;

    float4 qv = q4[(size_t)dst * 32 + lane];
    float4 Gr[4];
    {
        const float4* Gp = (const float4*)(g_G + (size_t)dst * 512 + h * 64 + p * 16);
#pragma unroll
        for (int i = 0; i < 4; i++) Gr[i] = Gp[i];
    }
    float cc = g_c[(size_t)dst * 8 + h];

    float denom = 0.f;
    float4 acc = make_float4(0.f, 0.f, 0.f, 0.f);

    int e = beg;
    for (; e + 2 <= end; e += 2) {
        int2 s0 = g_sedge[e];
        int2 s1 = g_sedge[e + 1];
        float4 kv0 = k4[(size_t)s0.x * 32 + lane];
        float4 kv1 = k4[(size_t)s1.x * 32 + lane];
        float4 vv0 = v4[(size_t)s0.x * 32 + lane];
        float4 vv1 = v4[(size_t)s1.x * 32 + lane];
        const float4* a0p = (const float4*)(ea + (size_t)s0.y * 64) + p * 4;
        const float4* a1p = (const float4*)(ea + (size_t)s1.y * 64) + p * 4;

        float t0 = qv.x * kv0.x + qv.y * kv0.y + qv.z * kv0.z + qv.w * kv0.w;
        float t1 = qv.x * kv1.x + qv.y * kv1.y + qv.z * kv1.z + qv.w * kv1.w;
#pragma unroll
        for (int i = 0; i < 4; i++) {
            float4 a0 = a0p[i];
            t0 += a0.x * Gr[i].x + a0.y * Gr[i].y + a0.z * Gr[i].z + a0.w * Gr[i].w;
        }
#pragma unroll
        for (int i = 0; i < 4; i++) {
            float4 a1 = a1p[i];
            t1 += a1.x * Gr[i].x + a1.y * Gr[i].y + a1.z * Gr[i].z + a1.w * Gr[i].w;
        }
        t0 += __shfl_xor_sync(0xffffffffu, t0, 1);
        t0 += __shfl_xor_sync(0xffffffffu, t0, 2);
        t1 += __shfl_xor_sync(0xffffffffu, t1, 1);
        t1 += __shfl_xor_sync(0xffffffffu, t1, 2);

        float ex0 = __expf((t0 + cc) * SCALE);
        float ex1 = __expf((t1 + cc) * SCALE);
        denom += ex0 + ex1;
        acc.x += ex0 * vv0.x + ex1 * vv1.x;
        acc.y += ex0 * vv0.y + ex1 * vv1.y;
        acc.z += ex0 * vv0.z + ex1 * vv1.z;
        acc.w += ex0 * vv0.w + ex1 * vv1.w;
    }
    if (e < end) {
        int2 s0 = g_sedge[e];
        float4 kv0 = k4[(size_t)s0.x * 32 + lane];
        float4 vv0 = v4[(size_t)s0.x * 32 + lane];
        const float4* a0p = (const float4*)(ea + (size_t)s0.y * 64) + p * 4;
        float t0 = qv.x * kv0.x + qv.y * kv0.y + qv.z * kv0.z + qv.w * kv0.w;
#pragma unroll
        for (int i = 0; i < 4; i++) {
            float4 a0 = a0p[i];
            t0 += a0.x * Gr[i].x + a0.y * Gr[i].y + a0.z * Gr[i].z + a0.w * Gr[i].w;
        }
        t0 += __shfl_xor_sync(0xffffffffu, t0, 1);
        t0 += __shfl_xor_sync(0xffffffffu, t0, 2);
        float ex0 = __expf((t0 + cc) * SCALE);
        denom += ex0;
        acc.x += ex0 * vv0.x;
        acc.y += ex0 * vv0.y;
        acc.z += ex0 * vv0.z;
        acc.w += ex0 * vv0.w;
    }

    float inv = (denom != 0.f) ? (1.f / denom) : 0.f;
    acc.x *= inv; acc.y *= inv; acc.z *= inv; acc.w *= inv;
    *(float4*)(g_acc + (size_t)dst * 128 + lane * 4) = acc;
}

// ---------------- launch ------------------------------------------------------
extern "C" void kernel_launch(void* const* d_in, const int* in_sizes, int n_in,
                              void* d_out, int out_size)
{
    const float* x  = (const float*)d_in[0];
    const float* ea = (const float*)d_in[1];
    const float* Wq = (const float*)d_in[2];
    const float* bq = (const float*)d_in[3];
    const float* Wk = (const float*)d_in[4];
    const float* bk = (const float*)d_in[5];
    const float* Wv = (const float*)d_in[6];
    const float* bv = (const float*)d_in[7];
    const float* We = (const float*)d_in[8];
    const float* be = (const float*)d_in[9];
    const float* Wo = (const float*)d_in[10];
    const float* bo = (const float*)d_in[11];
    const int*   ei = (const int*)d_in[12];

    int N = in_sizes[0] / DD;
    int E = in_sizes[12] / 2;

    float* qp;   cudaGetSymbolAddress((void**)&qp,   g_q);
    float* kp;   cudaGetSymbolAddress((void**)&kp,   g_k);
    float* vp;   cudaGetSymbolAddress((void**)&vp,   g_v);
    float* accp; cudaGetSymbolAddress((void**)&accp, g_acc);

    // sort edges by dst
    k_zero_cnt<<<(N + 255) / 256, 256>>>(N);
    k_hist<<<(E + 255) / 256, 256>>>(ei, E);
    k_scan<<<1, 1024>>>(N);
    k_scatter<<<(E + 255) / 256, 256>>>(ei, E);

    int gb = (N + 63) / 64;
    k_gemm128<<<gb, 256>>>(x, Wq, bq, qp, N);
    k_gemm128<<<gb, 256>>>(x, Wk, bk, kp, N);
    k_gemm128<<<gb, 256>>>(x, Wv, bv, vp, N);

    k_G<<<gb * 8, 256>>>(We, be, N);

    k_attn<<<(N * 32 + 127) / 128, 128>>>(ea, N);

    k_gemm128<<<gb, 256>>>(accp, Wo, bo, (float*)d_out, N);
}